// round 11
// baseline (speedup 1.0000x reference)
#include <cuda_runtime.h>
#include <cstdint>
#include <math.h>

#define D_DIM   2048
#define E_DIM   64
#define TOPK    2
#define M_TILE  64
#define KC      32
#define NCHUNK  (D_DIM / KC)    /* 64 */
#define THREADS 128
#define WROW    160             /* W row stride: 40 words ≡ 8 mod 32 */
#define W_BYTES (E_DIM * WROW)  /* 10240 */
#define AROW    288             /* A row stride: 72 words ≡ 8 mod 32 */
#define A_OFF   W_BYTES
#define A_BYTES (M_TILE * AROW) /* 18432 */
#define STAGE_B (W_BYTES + A_BYTES)   /* 28672 */
#define NSTAGE  3
#define SMEM_TOTAL (NSTAGE * STAGE_B) /* 86016 */
#define LG_STRIDE 65
#define TAU     2e-3f

__device__ __forceinline__ uint32_t smem_u32(const void* p) {
    uint32_t a;
    asm("{ .reg .u64 t; cvta.to.shared.u64 t, %1; cvt.u32.u64 %0, t; }" : "=r"(a) : "l"(p));
    return a;
}
__device__ __forceinline__ uint32_t f2tf32(float v) {
    uint32_t r;
    asm("cvt.rna.tf32.f32 %0, %1;" : "=r"(r) : "f"(v));
    return r;
}
__device__ __forceinline__ void mma_tf32(float* d, const uint32_t* a, uint32_t b0, uint32_t b1) {
    asm volatile(
        "mma.sync.aligned.m16n8k8.row.col.f32.tf32.tf32.f32 "
        "{%0,%1,%2,%3},{%4,%5,%6,%7},{%8,%9},{%0,%1,%2,%3};"
        : "+f"(d[0]), "+f"(d[1]), "+f"(d[2]), "+f"(d[3])
        : "r"(a[0]), "r"(a[1]), "r"(a[2]), "r"(a[3]), "r"(b0), "r"(b1));
}

extern __shared__ char smem[];

__global__ __launch_bounds__(THREADS, 2) void router_mma_kernel(
    const float* __restrict__ x, const float* __restrict__ W,
    float* __restrict__ out, int T)
{
    const uint32_t sb = smem_u32(smem);
    const int tid  = threadIdx.x;
    const int lane = tid & 31;
    const int wid  = tid >> 5;
    const int t0   = blockIdx.x * M_TILE;
    const int r    = lane >> 2;       // fragment row / expert-in-octet
    const int c    = lane & 3;        // fragment k index
    const int mq   = wid >> 1;        // m-half: rows mq*32 .. +31
    const int nh   = wid & 1;         // n-half: experts nh*32 .. +31

    // ---- W loader: thread -> (expert we = tid>>1, k-half part = tid&1) ----
    const int we   = tid >> 1;
    const int part = tid & 1;
    const float* wp = W + (size_t)we * D_DIM + part * 16;

    float acc[2][4][4];
#pragma unroll
    for (int mt = 0; mt < 2; ++mt)
#pragma unroll
        for (int nt = 0; nt < 4; ++nt)
#pragma unroll
            for (int d = 0; d < 4; ++d) acc[mt][nt][d] = 0.f;

    float4 wv[4];       // W chunk in flight: 16 k for expert we
    float4 av[4];       // A chunk in flight: idx = tid + 128j -> (row idx>>3, col4 idx&7)

#define LOAD_GL(kc)                                                           \
    {  _Pragma("unroll")                                                      \
       for (int j = 0; j < 4; ++j)                                            \
           wv[j] = *(const float4*)(wp + (kc) * KC + j * 4);                  \
       _Pragma("unroll")                                                      \
       for (int j = 0; j < 4; ++j) {                                          \
           int idx = tid + 128 * j;                                           \
           av[j] = *(const float4*)(x + (size_t)(t0 + (idx >> 3)) * D_DIM     \
                                    + (kc) * KC + (idx & 7) * 4);             \
       } }

    // W: hi-only, per g-block of 8 k: words {h0,h4,h1,h5},{h2,h6,h3,h7}
    // A: interleaved hi/lo pairs: row*AROW + k*8 -> {ah,al}
#define STS_STAGE(s)                                                          \
    {  float wf[16] = {wv[0].x, wv[0].y, wv[0].z, wv[0].w,                    \
                       wv[1].x, wv[1].y, wv[1].z, wv[1].w,                    \
                       wv[2].x, wv[2].y, wv[2].z, wv[2].w,                    \
                       wv[3].x, wv[3].y, wv[3].z, wv[3].w};                   \
       uint32_t h[16];                                                        \
       _Pragma("unroll")                                                      \
       for (int q = 0; q < 16; ++q) h[q] = f2tf32(wf[q]);                     \
       const uint32_t stage = sb + (s) * STAGE_B;                             \
       _Pragma("unroll")                                                      \
       for (int b = 0; b < 2; ++b) {                                          \
           uint32_t wa = stage + (uint32_t)(we * WROW + (part * 2 + b) * 32); \
           asm volatile("st.shared.v4.b32 [%0], {%1,%2,%3,%4};"               \
               :: "r"(wa), "r"(h[b*8+0]), "r"(h[b*8+4]),                      \
                  "r"(h[b*8+1]), "r"(h[b*8+5]) : "memory");                   \
           asm volatile("st.shared.v4.b32 [%0], {%1,%2,%3,%4};"               \
               :: "r"(wa + 16), "r"(h[b*8+2]), "r"(h[b*8+6]),                 \
                  "r"(h[b*8+3]), "r"(h[b*8+7]) : "memory");                   \
       }                                                                      \
       _Pragma("unroll")                                                      \
       for (int j = 0; j < 4; ++j) {                                          \
           int idx = tid + 128 * j;                                           \
           float vf[4] = {av[j].x, av[j].y, av[j].z, av[j].w};                \
           uint32_t ahh[4], all[4];                                           \
           _Pragma("unroll")                                                  \
           for (int q = 0; q < 4; ++q) {                                      \
               ahh[q] = f2tf32(vf[q]);                                        \
               all[q] = f2tf32(vf[q] - __uint_as_float(ahh[q]));              \
           }                                                                  \
           uint32_t aa = stage + A_OFF                                        \
                       + (uint32_t)((idx >> 3) * AROW + (idx & 7) * 32);      \
           asm volatile("st.shared.v4.b32 [%0], {%1,%2,%3,%4};"               \
               :: "r"(aa), "r"(ahh[0]), "r"(all[0]), "r"(ahh[1]), "r"(all[1]) : "memory"); \
           asm volatile("st.shared.v4.b32 [%0], {%1,%2,%3,%4};"               \
               :: "r"(aa + 16), "r"(ahh[2]), "r"(all[2]), "r"(ahh[3]), "r"(all[3]) : "memory"); \
       } }

#define COMPUTE(s)                                                            \
    {  const uint32_t stage = sb + (s) * STAGE_B;                             \
       const uint32_t bbase = stage + (uint32_t)((nh * 32 + r) * WROW + c * 8); \
       const uint32_t abase = stage + A_OFF                                   \
                            + (uint32_t)((mq * 32 + r) * AROW + c * 8);       \
       _Pragma("unroll")                                                      \
       for (int g = 0; g < 4; ++g) {                                          \
           uint32_t ah[2][4], al[2][4];                                       \
           _Pragma("unroll")                                                  \
           for (int mt = 0; mt < 2; ++mt)                                     \
           _Pragma("unroll")                                                  \
           for (int pos = 0; pos < 4; ++pos) {                                \
               uint32_t aaddr = abase                                         \
                   + (uint32_t)((mt * 16 + (pos & 1) * 8) * AROW              \
                   + g * 64 + (pos >> 1) * 32);                               \
               asm volatile("ld.shared.v2.b32 {%0,%1}, [%2];"                 \
                   : "=r"(ah[mt][pos]), "=r"(al[mt][pos]) : "r"(aaddr));      \
           }                                                                  \
           _Pragma("unroll")                                                  \
           for (int nt = 0; nt < 4; ++nt) {                                   \
               uint32_t b0, b1;                                               \
               uint32_t baddr = bbase + (uint32_t)(nt * 8 * WROW + g * 32);   \
               asm volatile("ld.shared.v2.b32 {%0,%1}, [%2];"                 \
                   : "=r"(b0), "=r"(b1) : "r"(baddr));                        \
               mma_tf32(acc[0][nt], ah[0], b0, b1);                           \
               mma_tf32(acc[1][nt], ah[1], b0, b1);                           \
               mma_tf32(acc[0][nt], al[0], b0, b1);                           \
               mma_tf32(acc[1][nt], al[1], b0, b1);                           \
           } } }

    // -------- prologue --------
    LOAD_GL(0);
    STS_STAGE(0);
    LOAD_GL(1);

    // -------- main loop: 3 stages, ONE barrier per chunk --------
    for (int kc = 0; kc < NCHUNK; ++kc) {
        if (kc + 1 < NCHUNK) STS_STAGE((kc + 1) % NSTAGE);  // regs hold kc+1
        if (kc + 2 < NCHUNK) LOAD_GL(kc + 2);
        __syncthreads();
        COMPUTE(kc % NSTAGE);
    }
    __syncthreads();    // all compute done before logits overwrite stage 0

    // -------- dump logits to smem --------
    float* lg = (float*)smem;
#pragma unroll
    for (int mt = 0; mt < 2; ++mt)
#pragma unroll
        for (int nt = 0; nt < 4; ++nt) {
            int row = mq * 32 + mt * 16 + r;
            int col = nh * 32 + nt * 8 + c * 2;
            lg[row * LG_STRIDE + col]           = acc[mt][nt][0];
            lg[row * LG_STRIDE + col + 1]       = acc[mt][nt][1];
            lg[(row + 8) * LG_STRIDE + col]     = acc[mt][nt][2];
            lg[(row + 8) * LG_STRIDE + col + 1] = acc[mt][nt][3];
        }
    __syncthreads();

    // -------- per-token epilogue: threads 0..63, one per token --------
    if (tid < M_TILE) {
        const float* lrow = &lg[tid * LG_STRIDE];

        // top-4 scan ('>' keeps lower index first on ties, matching lax.top_k)
        float m0 = -INFINITY, m1 = -INFINITY, m2 = -INFINITY, m3 = -INFINITY;
        int i0 = 0, i1 = 0, i2 = 0, i3 = 0;
#pragma unroll 8
        for (int e = 0; e < E_DIM; ++e) {
            float v = lrow[e];
            if (v > m0)      { m3=m2;i3=i2; m2=m1;i2=i1; m1=m0;i1=i0; m0=v;i0=e; }
            else if (v > m1) { m3=m2;i3=i2; m2=m1;i2=i1; m1=v;i1=e; }
            else if (v > m2) { m3=m2;i3=i2; m2=v;i2=e; }
            else if (v > m3) { m3=v;i3=e; }
        }

        // fp64 fixup for near-ties (ordering becomes exact)
        bool flag = (m0 - m1 < TAU) || (m1 - m2 < TAU) || (m2 - m3 < TAU);
        unsigned bal = __ballot_sync(0xFFFFFFFFu, flag);
        while (bal) {
            int src = __ffs(bal) - 1;
            bal &= bal - 1;
            int tt = t0 + (wid << 5) + src;
            int e4[4];
            e4[0] = __shfl_sync(0xFFFFFFFFu, i0, src);
            e4[1] = __shfl_sync(0xFFFFFFFFu, i1, src);
            e4[2] = __shfl_sync(0xFFFFFFFFu, i2, src);
            e4[3] = __shfl_sync(0xFFFFFFFFu, i3, src);
            double s4[4] = {0.0, 0.0, 0.0, 0.0};
            const float* xrow2 = x + (size_t)tt * D_DIM;
            for (int k = lane; k < D_DIM; k += 32) {
                double xv = (double)xrow2[k];
#pragma unroll
                for (int j = 0; j < 4; ++j)
                    s4[j] += xv * (double)W[(size_t)e4[j] * D_DIM + k];
            }
#pragma unroll
            for (int off = 16; off > 0; off >>= 1)
#pragma unroll
                for (int j = 0; j < 4; ++j)
                    s4[j] += __shfl_xor_sync(0xFFFFFFFFu, s4[j], off);
            if (lane == src) {
                for (int a = 0; a < 3; ++a)
                    for (int b = 0; b < 3 - a; ++b)
                        if (s4[b + 1] > s4[b]) {
                            double td = s4[b]; s4[b] = s4[b + 1]; s4[b + 1] = td;
                            int ti = e4[b]; e4[b] = e4[b + 1]; e4[b + 1] = ti;
                        }
                i0 = e4[0];
                i1 = e4[1];
            }
        }

        // softmax + outputs
        float ssum = 0.f;
#pragma unroll 8
        for (int e = 0; e < E_DIM; ++e) ssum += expf(lrow[e] - m0);
        const float inv  = 1.0f / ssum;
        const float p1   = expf(lrow[i0] - m0) * inv;
        const float p2   = expf(lrow[i1] - m0) * inv;
        const float rinv = 1.0f / (p1 + p2);

        const int t = t0 + tid;
        const size_t TT = (size_t)T;
        float* mask_o = out + (size_t)t * E_DIM;
        float* idx_o  = out + TT * E_DIM + (size_t)t * TOPK;
        float* rp_o   = out + TT * (E_DIM + TOPK) + (size_t)t * E_DIM;
        float* p_o    = out + TT * (2 * E_DIM + TOPK) + (size_t)t * E_DIM;

        idx_o[0] = (float)i0;
        idx_o[1] = (float)i1;

#pragma unroll 4
        for (int e = 0; e < E_DIM; e += 4) {
            float4 pv, mv, rv;
            float p;
            p = expf(lrow[e + 0] - m0) * inv;
            mv.x = (e + 0 == i0 || e + 0 == i1) ? 1.0f : 0.0f; pv.x = p; rv.x = mv.x * p * rinv;
            p = expf(lrow[e + 1] - m0) * inv;
            mv.y = (e + 1 == i0 || e + 1 == i1) ? 1.0f : 0.0f; pv.y = p; rv.y = mv.y * p * rinv;
            p = expf(lrow[e + 2] - m0) * inv;
            mv.z = (e + 2 == i0 || e + 2 == i1) ? 1.0f : 0.0f; pv.z = p; rv.z = mv.z * p * rinv;
            p = expf(lrow[e + 3] - m0) * inv;
            mv.w = (e + 3 == i0 || e + 3 == i1) ? 1.0f : 0.0f; pv.w = p; rv.w = mv.w * p * rinv;

            *(float4*)(mask_o + e) = mv;
            *(float4*)(p_o    + e) = pv;
            *(float4*)(rp_o   + e) = rv;
        }
    }
}

extern "C" void kernel_launch(void* const* d_in, const int* in_sizes, int n_in,
                              void* d_out, int out_size)
{
    const float* x = (const float*)d_in[0];
    const float* W = (const float*)d_in[1];
    float* out = (float*)d_out;

    const int T = in_sizes[0] / D_DIM;      // 16384
    const int grid = T / M_TILE;            // 256

    cudaFuncSetAttribute(router_mma_kernel,
                         cudaFuncAttributeMaxDynamicSharedMemorySize, SMEM_TOTAL);
    router_mma_kernel<<<grid, THREADS, SMEM_TOTAL>>>(x, W, out, T);
}

// round 13
// speedup vs baseline: 1.0633x; 1.0633x over previous
#include <cuda_runtime.h>
#include <cstdint>
#include <math.h>

#define D_DIM   2048
#define E_DIM   64
#define TOPK    2
#define M_TILE  64
#define KC      32
#define NCHUNK  (D_DIM / KC)    /* 64 */
#define THREADS 128
#define XROW    264             /* xs token-pair row stride (B), 66 words */
#define XS_BYTES (32 * XROW)    /* 8448 */
#define WDROW   640             /* wd k-row stride (B) */
#define WD_OFF  XS_BYTES
#define WD_BYTES (KC * WDROW)   /* 20480 */
#define STAGE_B (XS_BYTES + WD_BYTES)   /* 28928 */
#define NSTAGE  3
#define SMEM_TOTAL (NSTAGE * STAGE_B)   /* 86784 */
#define LG_STRIDE 65
#define TAU     1e-5f

__device__ __forceinline__ uint32_t smem_u32(const void* p) {
    uint32_t a;
    asm("{ .reg .u64 t; cvta.to.shared.u64 t, %1; cvt.u32.u64 %0, t; }" : "=r"(a) : "l"(p));
    return a;
}

extern __shared__ char smem[];

__global__ __launch_bounds__(THREADS, 2) void router_ffma2_kernel(
    const float* __restrict__ x, const float* __restrict__ W,
    float* __restrict__ out, int T)
{
    const uint32_t sb = smem_u32(smem);
    const int tid  = threadIdx.x;
    const int lane = tid & 31;
    const int wid  = tid >> 5;
    const int t0   = blockIdx.x * M_TILE;
    const int tpg  = lane >> 3;       // token-pair group 0..3
    const int ec   = lane & 7;        // expert octet 0..7

    // loader mapping (both x and W): row = tid>>1, part = tid&1
    const int lrow = tid >> 1;        // x token row / W expert row (0..63)
    const int lpart = tid & 1;
    const float* xp = x + (size_t)(t0 + lrow) * D_DIM + lpart * 16;
    const float* wp = W + (size_t)lrow * D_DIM + lpart * 16;

    // consumer a rows (token pairs): warp owns tokens wid*16..+15 -> tp wid*8..+7
    const int tp0 = wid * 8 + tpg * 2;

    unsigned long long acc[2][8];
#pragma unroll
    for (int i = 0; i < 2; ++i)
#pragma unroll
        for (int e = 0; e < 8; ++e) acc[i][e] = 0ull;

    float4 av[4], wv[4];    // chunk in flight: 16 k each

    // W duplicated-pair store: expert e -> pair p=e>>1, slot S(p)=(p>>2)*80+(p&3)*16
    const int wz  = lrow & 1;
    const int wpe = lrow >> 1;
    const uint32_t wslot = (uint32_t)((wpe >> 2) * 80 + (wpe & 3) * 16 + wz * 8);

#define LOAD_GL(kc)                                                           \
    {  _Pragma("unroll")                                                      \
       for (int j = 0; j < 4; ++j) {                                          \
           av[j] = *(const float4*)(xp + (kc) * KC + j * 4);                  \
           wv[j] = *(const float4*)(wp + (kc) * KC + j * 4);                  \
       } }

#define STS_STAGE(s)                                                          \
    {  const uint32_t stage = sb + (s) * STAGE_B;                             \
       _Pragma("unroll")                                                      \
       for (int j = 0; j < 4; ++j) {                                          \
           float va[4] = {av[j].x, av[j].y, av[j].z, av[j].w};                \
           float vw[4] = {wv[j].x, wv[j].y, wv[j].z, wv[j].w};                \
           _Pragma("unroll")                                                  \
           for (int q = 0; q < 4; ++q) {                                      \
               int kk = lpart * 16 + j * 4 + q;                               \
               uint32_t xa = stage + (uint32_t)((lrow >> 1) * XROW            \
                           + kk * 8 + (lrow & 1) * 4);                        \
               asm volatile("st.shared.f32 [%0], %1;"                         \
                   :: "r"(xa), "f"(va[q]) : "memory");                        \
               uint32_t wa = stage + WD_OFF + (uint32_t)(kk * WDROW) + wslot; \
               asm volatile("st.shared.v2.b32 [%0], {%1,%2};"                 \
                   :: "r"(wa), "r"(__float_as_uint(vw[q])),                   \
                      "r"(__float_as_uint(vw[q])) : "memory");                \
           } } }

#define COMPUTE(s)                                                            \
    {  const uint32_t stage = sb + (s) * STAGE_B;                             \
       const uint32_t abase = stage + (uint32_t)(tp0 * XROW);                 \
       const uint32_t bbase = stage + WD_OFF + (uint32_t)(ec * 80);           \
       _Pragma("unroll")                                                      \
       for (int kk = 0; kk < KC; ++kk) {                                      \
           unsigned long long a0, a1, b8[8];                                  \
           asm volatile("ld.shared.u64 %0, [%1];"                             \
               : "=l"(a0) : "r"(abase + (uint32_t)(kk * 8)));                 \
           asm volatile("ld.shared.u64 %0, [%1];"                             \
               : "=l"(a1) : "r"(abase + (uint32_t)(XROW + kk * 8)));          \
           _Pragma("unroll")                                                  \
           for (int q = 0; q < 4; ++q)                                        \
               asm volatile("ld.shared.v2.u64 {%0,%1}, [%2];"                 \
                   : "=l"(b8[2*q]), "=l"(b8[2*q+1])                           \
                   : "r"(bbase + (uint32_t)(kk * WDROW + q * 16)));           \
           _Pragma("unroll")                                                  \
           for (int e = 0; e < 8; ++e) {                                      \
               asm("fma.rn.f32x2 %0, %1, %2, %0;"                             \
                   : "+l"(acc[0][e]) : "l"(a0), "l"(b8[e]));                  \
               asm("fma.rn.f32x2 %0, %1, %2, %0;"                             \
                   : "+l"(acc[1][e]) : "l"(a1), "l"(b8[e]));                  \
           } } }

    // -------- prologue --------
    LOAD_GL(0);
    STS_STAGE(0);
    LOAD_GL(1);

    // -------- main loop: 3 stages, one barrier per chunk --------
    for (int kc = 0; kc < NCHUNK; ++kc) {
        if (kc + 1 < NCHUNK) STS_STAGE((kc + 1) % NSTAGE);   // regs hold kc+1
        if (kc + 2 < NCHUNK) LOAD_GL(kc + 2);
        __syncthreads();
        COMPUTE(kc % NSTAGE);
    }
    __syncthreads();    // all compute done before logits overwrite stage 0

    // -------- dump logits: acc[i][e] = tokens (2tp_i, 2tp_i+1), expert ec*8+e
    float* lg = (float*)smem;
#pragma unroll
    for (int i = 0; i < 2; ++i) {
        int trow = wid * 16 + tpg * 4 + 2 * i;   // block-local token
#pragma unroll
        for (int e = 0; e < 8; ++e) {
            float lo, hi;
            asm("mov.b64 {%0,%1}, %2;" : "=f"(lo), "=f"(hi) : "l"(acc[i][e]));
            lg[trow * LG_STRIDE + ec * 8 + e]       = lo;
            lg[(trow + 1) * LG_STRIDE + ec * 8 + e] = hi;
        }
    }
    __syncthreads();

    // -------- per-token epilogue: threads 0..63 --------
    if (tid < M_TILE) {
        const float* lrow2 = &lg[tid * LG_STRIDE];

        // top-4 scan ('>' keeps lower index first on ties, matching lax.top_k)
        float m0 = -INFINITY, m1 = -INFINITY, m2 = -INFINITY, m3 = -INFINITY;
        int i0 = 0, i1 = 0, i2 = 0, i3 = 0;
#pragma unroll 8
        for (int e = 0; e < E_DIM; ++e) {
            float v = lrow2[e];
            if (v > m0)      { m3=m2;i3=i2; m2=m1;i2=i1; m1=m0;i1=i0; m0=v;i0=e; }
            else if (v > m1) { m3=m2;i3=i2; m2=m1;i2=i1; m1=v;i1=e; }
            else if (v > m2) { m3=m2;i3=i2; m2=v;i2=e; }
            else if (v > m3) { m3=v;i3=e; }
        }

        // fp64 fixup for near-ties (cheap insurance; flags ~0.003% of tokens)
        bool flag = (m0 - m1 < TAU) || (m1 - m2 < TAU) || (m2 - m3 < TAU);
        unsigned bal = __ballot_sync(0xFFFFFFFFu, flag);
        while (bal) {
            int src = __ffs(bal) - 1;
            bal &= bal - 1;
            int tt = t0 + (wid << 5) + src;
            int e4[4];
            e4[0] = __shfl_sync(0xFFFFFFFFu, i0, src);
            e4[1] = __shfl_sync(0xFFFFFFFFu, i1, src);
            e4[2] = __shfl_sync(0xFFFFFFFFu, i2, src);
            e4[3] = __shfl_sync(0xFFFFFFFFu, i3, src);
            double s4[4] = {0.0, 0.0, 0.0, 0.0};
            const float* xrow2 = x + (size_t)tt * D_DIM;
            for (int k = lane; k < D_DIM; k += 32) {
                double xv = (double)xrow2[k];
#pragma unroll
                for (int j = 0; j < 4; ++j)
                    s4[j] += xv * (double)W[(size_t)e4[j] * D_DIM + k];
            }
#pragma unroll
            for (int off = 16; off > 0; off >>= 1)
#pragma unroll
                for (int j = 0; j < 4; ++j)
                    s4[j] += __shfl_xor_sync(0xFFFFFFFFu, s4[j], off);
            if (lane == src) {
                for (int a = 0; a < 3; ++a)
                    for (int b = 0; b < 3 - a; ++b)
                        if (s4[b + 1] > s4[b]) {
                            double td = s4[b]; s4[b] = s4[b + 1]; s4[b + 1] = td;
                            int ti = e4[b]; e4[b] = e4[b + 1]; e4[b + 1] = ti;
                        }
                i0 = e4[0];
                i1 = e4[1];
            }
        }

        // softmax + outputs
        float ssum = 0.f;
#pragma unroll 8
        for (int e = 0; e < E_DIM; ++e) ssum += expf(lrow2[e] - m0);
        const float inv  = 1.0f / ssum;
        const float p1   = expf(lrow2[i0] - m0) * inv;
        const float p2   = expf(lrow2[i1] - m0) * inv;
        const float rinv = 1.0f / (p1 + p2);

        const int t = t0 + tid;
        const size_t TT = (size_t)T;
        float* mask_o = out + (size_t)t * E_DIM;
        float* idx_o  = out + TT * E_DIM + (size_t)t * TOPK;
        float* rp_o   = out + TT * (E_DIM + TOPK) + (size_t)t * E_DIM;
        float* p_o    = out + TT * (2 * E_DIM + TOPK) + (size_t)t * E_DIM;

        idx_o[0] = (float)i0;
        idx_o[1] = (float)i1;

#pragma unroll 4
        for (int e = 0; e < E_DIM; e += 4) {
            float4 pv, mv, rv;
            float p;
            p = expf(lrow2[e + 0] - m0) * inv;
            mv.x = (e + 0 == i0 || e + 0 == i1) ? 1.0f : 0.0f; pv.x = p; rv.x = mv.x * p * rinv;
            p = expf(lrow2[e + 1] - m0) * inv;
            mv.y = (e + 1 == i0 || e + 1 == i1) ? 1.0f : 0.0f; pv.y = p; rv.y = mv.y * p * rinv;
            p = expf(lrow2[e + 2] - m0) * inv;
            mv.z = (e + 2 == i0 || e + 2 == i1) ? 1.0f : 0.0f; pv.z = p; rv.z = mv.z * p * rinv;
            p = expf(lrow2[e + 3] - m0) * inv;
            mv.w = (e + 3 == i0 || e + 3 == i1) ? 1.0f : 0.0f; pv.w = p; rv.w = mv.w * p * rinv;

            *(float4*)(mask_o + e) = mv;
            *(float4*)(p_o    + e) = pv;
            *(float4*)(rp_o   + e) = rv;
        }
    }
}

extern "C" void kernel_launch(void* const* d_in, const int* in_sizes, int n_in,
                              void* d_out, int out_size)
{
    const float* x = (const float*)d_in[0];
    const float* W = (const float*)d_in[1];
    float* out = (float*)d_out;

    const int T = in_sizes[0] / D_DIM;      // 16384
    const int grid = T / M_TILE;            // 256

    cudaFuncSetAttribute(router_ffma2_kernel,
                         cudaFuncAttributeMaxDynamicSharedMemorySize, SMEM_TOTAL);
    router_ffma2_kernel<<<grid, THREADS, SMEM_TOTAL>>>(x, W, out, T);
}

// round 14
// speedup vs baseline: 2.0302x; 1.9093x over previous
#include <cuda_runtime.h>
#include <cstdint>
#include <math.h>

#define D_DIM   2048
#define E_DIM   64
#define TOPK    2
#define M_TILE  128
#define THREADS 256
#define BK      32                    /* k per half per chunk */
#define NCH     32                    /* (2048/2)/BK */
#define ROWB    144                   /* row stride bytes (36 words ≡ 4 mod 32) */
#define XH_B    (M_TILE * ROWB)       /* 18432 per x half */
#define WOFF    (2 * XH_B)            /* 36864 */
#define WH_B    (E_DIM * ROWB)        /* 9216 per W half */
#define STAGE_B (2 * XH_B + 2 * WH_B) /* 55296 */
#define NSTAGE  3
#define SMEM_TOTAL (NSTAGE * STAGE_B) /* 165888 */
#define LG_STRIDE 65
#define LGB_OFF (M_TILE * LG_STRIDE * 4)   /* 33280 */
#define TAU     1e-5f

__device__ __forceinline__ uint32_t smem_u32(const void* p) {
    uint32_t a;
    asm("{ .reg .u64 t; cvta.to.shared.u64 t, %1; cvt.u32.u64 %0, t; }" : "=r"(a) : "l"(p));
    return a;
}
#define CP16(d, s) asm volatile("cp.async.ca.shared.global [%0], [%1], 16;" \
    :: "r"(d), "l"(s) : "memory")
#define CP_COMMIT() asm volatile("cp.async.commit_group;" ::: "memory")
#define CP_WAIT1()  asm volatile("cp.async.wait_group 1;" ::: "memory")

extern __shared__ char smem[];

__global__ __launch_bounds__(THREADS, 1) void router_ffma2_kernel(
    const float* __restrict__ x, const float* __restrict__ W,
    float* __restrict__ out, int T)
{
    const uint32_t sb = smem_u32(smem);
    const int tid  = threadIdx.x;
    const int lane = tid & 31;
    const int wid  = tid >> 5;
    const int t0   = blockIdx.x * M_TILE;
    const int tg   = lane >> 3;       // token group 0..3 (tokens tg + 4i)
    const int eg   = lane & 7;        // expert group 0..7 (experts eg + 8j)
    const int mg   = wid & 3;         // m-group: tokens mg*32 ..
    const int kh   = wid >> 2;        // k-half 0/1

    // loader mapping: x: idx=tid+256j (j<4): row=idx>>3 (128), col16=idx&7
    //                 W: idx=tid+256j (j<2): row=idx>>3 (64),  col16=idx&7
    const int xrow = tid >> 3, xcol = tid & 7;

    unsigned long long acc[8][8];
#pragma unroll
    for (int i = 0; i < 8; ++i)
#pragma unroll
        for (int j = 0; j < 8; ++j) acc[i][j] = 0ull;

#define ISSUE(kc)                                                             \
    {  const uint32_t stg = sb + ((kc) % NSTAGE) * STAGE_B;                   \
       _Pragma("unroll")                                                      \
       for (int h = 0; h < 2; ++h) {                                          \
           _Pragma("unroll")                                                  \
           for (int j = 0; j < 4; ++j) {                                      \
               int row = xrow + 32 * j;                                       \
               uint32_t d = stg + (uint32_t)(h * XH_B + row * ROWB + xcol * 16); \
               const float* s = x + (size_t)(t0 + row) * D_DIM                \
                              + h * 1024 + (kc) * BK + xcol * 4;              \
               CP16(d, s);                                                    \
           }                                                                  \
           _Pragma("unroll")                                                  \
           for (int j = 0; j < 2; ++j) {                                      \
               int idx = tid + 256 * j;                                       \
               int row = idx >> 3, col = idx & 7;                             \
               uint32_t d = stg + (uint32_t)(WOFF + h * WH_B + row * ROWB + col * 16); \
               const float* s = W + (size_t)row * D_DIM                       \
                              + h * 1024 + (kc) * BK + col * 4;               \
               CP16(d, s);                                                    \
           } } }

#define COMPUTE(s)                                                            \
    {  const uint32_t stg = sb + (s) * STAGE_B;                               \
       const uint32_t ab = stg + (uint32_t)(kh * XH_B + (mg * 32 + tg) * ROWB); \
       const uint32_t bb = stg + (uint32_t)(WOFF + kh * WH_B + eg * ROWB);    \
       _Pragma("unroll")                                                      \
       for (int kp = 0; kp < BK / 2; ++kp) {                                  \
           unsigned long long a[8], b[8];                                     \
           _Pragma("unroll")                                                  \
           for (int i = 0; i < 8; ++i)                                        \
               asm volatile("ld.shared.u64 %0, [%1];" : "=l"(a[i])            \
                   : "r"(ab + (uint32_t)(i * 4 * ROWB + kp * 8)));            \
           _Pragma("unroll")                                                  \
           for (int j = 0; j < 8; ++j)                                        \
               asm volatile("ld.shared.u64 %0, [%1];" : "=l"(b[j])            \
                   : "r"(bb + (uint32_t)(j * 8 * ROWB + kp * 8)));            \
           _Pragma("unroll")                                                  \
           for (int i = 0; i < 8; ++i)                                        \
           _Pragma("unroll")                                                  \
           for (int j = 0; j < 8; ++j)                                        \
               asm("fma.rn.f32x2 %0, %1, %2, %0;"                             \
                   : "+l"(acc[i][j]) : "l"(a[i]), "l"(b[j]));                 \
       } }

    // -------- prologue --------
    ISSUE(0); CP_COMMIT();
    ISSUE(1); CP_COMMIT();

    // -------- main loop --------
    for (int kc = 0; kc < NCH; ++kc) {
        CP_WAIT1();
        __syncthreads();
        COMPUTE(kc % NSTAGE);
        __syncthreads();
        if (kc + 2 < NCH) ISSUE(kc + 2);
        CP_COMMIT();          // empty commits keep group accounting uniform
    }

    // -------- dump partial logits (per k-half) --------
    float* lg = (float*)smem;           // lgA at 0, lgB at LGB_OFF
    float* lgh = (float*)(smem + kh * LGB_OFF);
#pragma unroll
    for (int i = 0; i < 8; ++i) {
        int trow = mg * 32 + tg + 4 * i;
#pragma unroll
        for (int j = 0; j < 8; ++j) {
            float lo, hi;
            asm("mov.b64 {%0,%1}, %2;" : "=f"(lo), "=f"(hi) : "l"(acc[i][j]));
            lgh[trow * LG_STRIDE + eg + 8 * j] = lo + hi;
        }
    }
    __syncthreads();

    // -------- per-token epilogue: threads 0..127 --------
    if (tid < M_TILE) {
        float lrow[E_DIM];
#pragma unroll 8
        for (int e = 0; e < E_DIM; ++e)
            lrow[e] = lg[tid * LG_STRIDE + e] + lg[(LGB_OFF / 4) + tid * LG_STRIDE + e];

        // top-4 scan ('>' keeps lower index first on ties, matching lax.top_k)
        float m0 = -INFINITY, m1 = -INFINITY, m2 = -INFINITY, m3 = -INFINITY;
        int i0 = 0, i1 = 0, i2 = 0, i3 = 0;
#pragma unroll 8
        for (int e = 0; e < E_DIM; ++e) {
            float v = lrow[e];
            if (v > m0)      { m3=m2;i3=i2; m2=m1;i2=i1; m1=m0;i1=i0; m0=v;i0=e; }
            else if (v > m1) { m3=m2;i3=i2; m2=m1;i2=i1; m1=v;i1=e; }
            else if (v > m2) { m3=m2;i3=i2; m2=v;i2=e; }
            else if (v > m3) { m3=v;i3=e; }
        }

        // fp64 fixup for near-ties (cheap insurance)
        bool flag = (m0 - m1 < TAU) || (m1 - m2 < TAU) || (m2 - m3 < TAU);
        unsigned bal = __ballot_sync(0xFFFFFFFFu, flag);
        while (bal) {
            int src = __ffs(bal) - 1;
            bal &= bal - 1;
            int tt = t0 + (wid << 5) + src;
            int e4[4];
            e4[0] = __shfl_sync(0xFFFFFFFFu, i0, src);
            e4[1] = __shfl_sync(0xFFFFFFFFu, i1, src);
            e4[2] = __shfl_sync(0xFFFFFFFFu, i2, src);
            e4[3] = __shfl_sync(0xFFFFFFFFu, i3, src);
            double s4[4] = {0.0, 0.0, 0.0, 0.0};
            const float* xrow2 = x + (size_t)tt * D_DIM;
            for (int k = lane; k < D_DIM; k += 32) {
                double xv = (double)xrow2[k];
#pragma unroll
                for (int j = 0; j < 4; ++j)
                    s4[j] += xv * (double)W[(size_t)e4[j] * D_DIM + k];
            }
#pragma unroll
            for (int off = 16; off > 0; off >>= 1)
#pragma unroll
                for (int j = 0; j < 4; ++j)
                    s4[j] += __shfl_xor_sync(0xFFFFFFFFu, s4[j], off);
            if (lane == src) {
                for (int a = 0; a < 3; ++a)
                    for (int b = 0; b < 3 - a; ++b)
                        if (s4[b + 1] > s4[b]) {
                            double td = s4[b]; s4[b] = s4[b + 1]; s4[b + 1] = td;
                            int ti = e4[b]; e4[b] = e4[b + 1]; e4[b + 1] = ti;
                        }
                i0 = e4[0];
                i1 = e4[1];
            }
        }

        // softmax + outputs
        float ssum = 0.f;
#pragma unroll 8
        for (int e = 0; e < E_DIM; ++e) ssum += expf(lrow[e] - m0);
        const float inv  = 1.0f / ssum;
        const float p1   = expf(lrow[i0] - m0) * inv;
        const float p2   = expf(lrow[i1] - m0) * inv;
        const float rinv = 1.0f / (p1 + p2);

        const int t = t0 + tid;
        const size_t TT = (size_t)T;
        float* mask_o = out + (size_t)t * E_DIM;
        float* idx_o  = out + TT * E_DIM + (size_t)t * TOPK;
        float* rp_o   = out + TT * (E_DIM + TOPK) + (size_t)t * E_DIM;
        float* p_o    = out + TT * (2 * E_DIM + TOPK) + (size_t)t * E_DIM;

        idx_o[0] = (float)i0;
        idx_o[1] = (float)i1;

#pragma unroll 4
        for (int e = 0; e < E_DIM; e += 4) {
            float4 pv, mv, rv;
            float p;
            p = expf(lrow[e + 0] - m0) * inv;
            mv.x = (e + 0 == i0 || e + 0 == i1) ? 1.0f : 0.0f; pv.x = p; rv.x = mv.x * p * rinv;
            p = expf(lrow[e + 1] - m0) * inv;
            mv.y = (e + 1 == i0 || e + 1 == i1) ? 1.0f : 0.0f; pv.y = p; rv.y = mv.y * p * rinv;
            p = expf(lrow[e + 2] - m0) * inv;
            mv.z = (e + 2 == i0 || e + 2 == i1) ? 1.0f : 0.0f; pv.z = p; rv.z = mv.z * p * rinv;
            p = expf(lrow[e + 3] - m0) * inv;
            mv.w = (e + 3 == i0 || e + 3 == i1) ? 1.0f : 0.0f; pv.w = p; rv.w = mv.w * p * rinv;

            *(float4*)(mask_o + e) = mv;
            *(float4*)(p_o    + e) = pv;
            *(float4*)(rp_o   + e) = rv;
        }
    }
}

extern "C" void kernel_launch(void* const* d_in, const int* in_sizes, int n_in,
                              void* d_out, int out_size)
{
    const float* x = (const float*)d_in[0];
    const float* W = (const float*)d_in[1];
    float* out = (float*)d_out;

    const int T = in_sizes[0] / D_DIM;      // 16384
    const int grid = T / M_TILE;            // 128

    cudaFuncSetAttribute(router_ffma2_kernel,
                         cudaFuncAttributeMaxDynamicSharedMemorySize, SMEM_TOTAL);
    router_ffma2_kernel<<<grid, THREADS, SMEM_TOTAL>>>(x, W, out, T);
}